// round 10
// baseline (speedup 1.0000x reference)
#include <cuda_runtime.h>
#include <cuda_fp16.h>
#include <math.h>
#include <stdint.h>

#define BDIM  16384
#define H_DIM 1024
#define A_DIM 20
#define K_DIM 4096

#define BM 64
#define BN 128
#define BK 32
#define NSTAGE (K_DIM / BK)      // 128
#define STAGEB 24576             // 24 KB: Ahi 4K | Alo 4K | Bhi 8K | Blo 8K
#define W_SCALE 2048.0f
#define INV_W_SCALE (1.0f / 2048.0f)

// Static scratch (no allocations allowed)
__device__ __align__(1024) float  g_hidden[(size_t)BDIM * H_DIM];  // 64 MB
__device__ __align__(1024) __half g_Ahi[(size_t)BDIM * K_DIM];     // 128 MB
__device__ __align__(1024) __half g_Alo[(size_t)BDIM * K_DIM];     // 128 MB
__device__ __align__(1024) __half g_Bhi[(size_t)H_DIM * K_DIM];    // 8 MB (2048*W1^T hi)
__device__ __align__(1024) __half g_Blo[(size_t)H_DIM * K_DIM];    // 8 MB

// ---------------------------------------------------------------- helpers --
__device__ __forceinline__ uint32_t smem_u32(const void* p) {
    uint32_t a;
    asm("{ .reg .u64 t; cvta.to.shared.u64 t, %1; cvt.u32.u64 %0, t; }"
        : "=r"(a) : "l"(p));
    return a;
}
__device__ __forceinline__ void cp_async16(uint32_t dst, const void* src) {
    asm volatile("cp.async.cg.shared.global [%0], [%1], 16;" :: "r"(dst), "l"(src));
}

#define LDSM4(r, addr) \
    asm volatile("ldmatrix.sync.aligned.m8n8.x4.shared.b16 {%0,%1,%2,%3}, [%4];" \
        : "=r"((r)[0]), "=r"((r)[1]), "=r"((r)[2]), "=r"((r)[3]) : "r"(addr))

__device__ __forceinline__ void mma_f16(float* c, const uint32_t* a, const uint32_t* b) {
    asm volatile(
        "mma.sync.aligned.m16n8k16.row.col.f32.f16.f16.f32 "
        "{%0,%1,%2,%3},{%4,%5,%6,%7},{%8,%9},{%0,%1,%2,%3};"
        : "+f"(c[0]), "+f"(c[1]), "+f"(c[2]), "+f"(c[3])
        : "r"(a[0]), "r"(a[1]), "r"(a[2]), "r"(a[3]), "r"(b[0]), "r"(b[1]));
}

// Two logical 32-half rows packed per 128B smem row, SW128 within the row.
__device__ __forceinline__ uint32_t tile_off(int r, int s) {
    const uint32_t cc = ((uint32_t)(r & 1) << 2) + (uint32_t)s;
    return (uint32_t)(r >> 1) * 128u + ((cc ^ ((uint32_t)(r >> 1) & 7u)) << 4);
}

// ------------------------------------------------------------- pre-passes --
__global__ __launch_bounds__(256) void splitA_kernel(
    const float* __restrict__ x0, const float* __restrict__ x1,
    const float* __restrict__ x2, const float* __restrict__ x3)
{
    const size_t i = (size_t)blockIdx.x * blockDim.x + threadIdx.x;  // float4 idx
    if (i >= (size_t)BDIM * K_DIM / 4) return;
    const size_t m = i >> 10;
    const int kq = (int)(i & 1023);
    const int part = kq >> 8;
    const int kin = (kq & 255) * 4;
    const float* xs = part == 0 ? x0 : part == 1 ? x1 : part == 2 ? x2 : x3;
    float4 a = *(const float4*)(xs + m * H_DIM + kin);

    __half h0 = __float2half_rn(a.x), h1 = __float2half_rn(a.y);
    __half h2 = __float2half_rn(a.z), h3 = __float2half_rn(a.w);
    __half l0 = __float2half_rn(a.x - __half2float(h0));
    __half l1 = __float2half_rn(a.y - __half2float(h1));
    __half l2 = __float2half_rn(a.z - __half2float(h2));
    __half l3 = __float2half_rn(a.w - __half2float(h3));

    __half2* ph = (__half2*)(g_Ahi + i * 4);
    __half2* pl = (__half2*)(g_Alo + i * 4);
    ph[0] = __halves2half2(h0, h1); ph[1] = __halves2half2(h2, h3);
    pl[0] = __halves2half2(l0, l1); pl[1] = __halves2half2(l2, l3);
}

__global__ void splitB_kernel(const float* __restrict__ W1)
{
    __shared__ float tile[32][33];
    const int k0 = blockIdx.y * 32;
    const int n0 = blockIdx.x * 32;
    const int tx = threadIdx.x, ty = threadIdx.y;
#pragma unroll
    for (int j = 0; j < 32; j += 8)
        tile[ty + j][tx] = W1[(size_t)(k0 + ty + j) * H_DIM + n0 + tx];
    __syncthreads();
#pragma unroll
    for (int j = 0; j < 32; j += 8) {
        const int n = n0 + ty + j, k = k0 + tx;
        const float v = tile[tx][ty + j] * W_SCALE;
        const __half h = __float2half_rn(v);
        g_Bhi[(size_t)n * K_DIM + k] = h;
        g_Blo[(size_t)n * K_DIM + k] = __float2half_rn(v - __half2float(h));
    }
}

// ------------------------------------------- stage 1: fp16x3 mma GEMM ------
// 64x128x32 tiles, 256 threads, 2 CTAs/SM, warp tile 32x32.
__global__ __launch_bounds__(256, 2) void gemm1_fp16_kernel(const float* __restrict__ b1)
{
    extern __shared__ char smem[];
    const uint32_t sb = smem_u32(smem);
    const int tid  = threadIdx.x;
    const int wid  = tid >> 5;
    const int lane = tid & 31;
    const int wm = wid & 1;     // 2 m-tiles of 32
    const int wn = wid >> 1;    // 4 n-tiles of 32
    const int bm = blockIdx.y * BM;
    const int bn = blockIdx.x * BN;

    // loader: A 512 chunks (2 planes x 64 rows x 4 segs), B 1024; 2+4/thread
    auto load_stage = [&](int t) {
        const uint32_t base = sb + (t & 1) * STAGEB;
        const int k0 = t * BK;
#pragma unroll
        for (int c = 0; c < 2; c++) {
            const int idx = c * 256 + tid;
            const int plane = idx >> 8, rem = idx & 255;
            const int r = rem >> 2, seg = rem & 3;
            const __half* gp = plane ? g_Alo : g_Ahi;
            cp_async16(base + plane * 4096 + tile_off(r, seg),
                       gp + (size_t)(bm + r) * K_DIM + k0 + seg * 8);
        }
#pragma unroll
        for (int c = 0; c < 4; c++) {
            const int idx = c * 256 + tid;
            const int plane = idx >> 9, rem = idx & 511;
            const int r = rem >> 2, seg = rem & 3;
            const __half* gp = plane ? g_Blo : g_Bhi;
            cp_async16(base + 8192 + plane * 8192 + tile_off(r, seg),
                       gp + (size_t)(bn + r) * K_DIM + k0 + seg * 8);
        }
        asm volatile("cp.async.commit_group;" ::: "memory");
    };

    float acc[2][4][4];
#pragma unroll
    for (int i = 0; i < 2; i++)
#pragma unroll
        for (int j = 0; j < 4; j++)
#pragma unroll
            for (int q = 0; q < 4; q++) acc[i][j][q] = 0.f;

    load_stage(0);
    load_stage(1);
    asm volatile("cp.async.wait_group 1;" ::: "memory");
    __syncthreads();

    const int rA  = wm * 32 + (lane & 15);
    const int rB0 = wn * 32 + (lane & 15);
    const int sseg = lane >> 4;

    for (int t = 0; t < NSTAGE; ++t) {
        const uint32_t base = sb + (t & 1) * STAGEB;
#pragma unroll
        for (int ks = 0; ks < 2; ks++) {
            const int kseg = ks * 2 + sseg;          // 0..3
            uint32_t ah[2][4], al[2][4];
#pragma unroll
            for (int i = 0; i < 2; i++) {
                const int r = rA + i * 16;
                const uint32_t addr = base + tile_off(r, kseg);
                LDSM4(ah[i], addr);
                LDSM4(al[i], addr + 4096);
            }
            uint32_t bb[2][4];
#pragma unroll
            for (int p = 0; p < 2; p++) {
                const int r = rB0 + p * 16;
                LDSM4(bb[p], base + 8192 + tile_off(r, kseg));
            }
#pragma unroll
            for (int j = 0; j < 4; j++) {
                uint32_t bf[2] = { bb[j >> 1][j & 1], bb[j >> 1][(j & 1) + 2] };
                mma_f16(acc[0][j], ah[0], bf);
                mma_f16(acc[1][j], ah[1], bf);
                mma_f16(acc[0][j], al[0], bf);
                mma_f16(acc[1][j], al[1], bf);
            }
#pragma unroll
            for (int p = 0; p < 2; p++) {
                const int r = rB0 + p * 16;
                LDSM4(bb[p], base + 16384 + tile_off(r, kseg));
            }
#pragma unroll
            for (int j = 0; j < 4; j++) {
                uint32_t bf[2] = { bb[j >> 1][j & 1], bb[j >> 1][(j & 1) + 2] };
                mma_f16(acc[0][j], ah[0], bf);
                mma_f16(acc[1][j], ah[1], bf);
            }
        }
        __syncthreads();
        if (t + 2 < NSTAGE) {
            load_stage(t + 2);
            asm volatile("cp.async.wait_group 1;" ::: "memory");
        } else {
            asm volatile("cp.async.wait_group 0;" ::: "memory");
        }
        __syncthreads();
    }

    // epilogue: scale back, +b1, tanh
    const int g  = lane >> 2;
    const int tq = lane & 3;
#pragma unroll
    for (int j = 0; j < 4; j++) {
        const int col = bn + wn * 32 + j * 8 + tq * 2;
        const float bb0 = __ldg(&b1[col]);
        const float bb1 = __ldg(&b1[col + 1]);
#pragma unroll
        for (int i = 0; i < 2; i++) {
            const int row0 = bm + wm * 32 + i * 16 + g;
            float2 v0, v1;
            v0.x = tanhf(fmaf(acc[i][j][0], INV_W_SCALE, bb0));
            v0.y = tanhf(fmaf(acc[i][j][1], INV_W_SCALE, bb1));
            v1.x = tanhf(fmaf(acc[i][j][2], INV_W_SCALE, bb0));
            v1.y = tanhf(fmaf(acc[i][j][3], INV_W_SCALE, bb1));
            *(float2*)(g_hidden + (size_t)row0 * H_DIM + col)       = v0;
            *(float2*)(g_hidden + (size_t)(row0 + 8) * H_DIM + col) = v1;
        }
    }
}

// ------------------------------------------------------------- stage 2 ----
// 512 threads (16 warps), 80KB smem W2^T, 2 rows per warp, float4 LDS.
__global__ __launch_bounds__(512) void stage2_kernel(
    const float* __restrict__ W2, const float* __restrict__ b2,
    const void* __restrict__ valid_mask,
    const int* __restrict__ real_actions,
    float* __restrict__ out, int B, int write_pred)
{
    extern __shared__ float W2t[];  // [20][1024]
    __shared__ int s_mode;
    if (threadIdx.x == 0) {
        const unsigned int* m = (const unsigned int*)valid_mask;
        bool f32 = false, bf16 = false, multi = false;
#pragma unroll
        for (int i = 0; i < 64; i++) {
            unsigned int w = m[i];
            if (w == 0x3F800000u) f32 = true;
            else if (w == 0x3F803F80u || w == 0x00003F80u) bf16 = true;
            else if (w > 1u) multi = true;
        }
        s_mode = bf16 ? 3 : f32 ? 2 : multi ? 0 : 1;
    }
    for (int i = threadIdx.x; i < A_DIM * H_DIM; i += blockDim.x) {
        const int a = i >> 10;
        const int k = i & 1023;
        W2t[a * H_DIM + k] = W2[k * A_DIM + a];
    }
    __syncthreads();

    const int warp = threadIdx.x >> 5;
    const int lane = threadIdx.x & 31;
    const int row0 = blockIdx.x * 32 + warp * 2;
    if (row0 >= B) return;

    float acc0[A_DIM], acc1[A_DIM];
#pragma unroll
    for (int a = 0; a < A_DIM; a++) { acc0[a] = 0.f; acc1[a] = 0.f; }

    const float* h0 = g_hidden + (size_t)row0 * H_DIM;
    const float* h1 = h0 + H_DIM;
#pragma unroll
    for (int j = 0; j < 8; j++) {
        const int k = j * 128 + lane * 4;
        const float4 v0 = *(const float4*)(h0 + k);
        const float4 v1 = *(const float4*)(h1 + k);
#pragma unroll
        for (int a = 0; a < A_DIM; a++) {
            const float4 w = *(const float4*)(W2t + a * H_DIM + k);
            acc0[a] = fmaf(v0.x, w.x, fmaf(v0.y, w.y, fmaf(v0.z, w.z, fmaf(v0.w, w.w, acc0[a]))));
            acc1[a] = fmaf(v1.x, w.x, fmaf(v1.y, w.y, fmaf(v1.z, w.z, fmaf(v1.w, w.w, acc1[a]))));
        }
    }

#pragma unroll
    for (int off = 16; off > 0; off >>= 1)
#pragma unroll
        for (int a = 0; a < A_DIM; a++) {
            acc0[a] += __shfl_xor_sync(0xffffffffu, acc0[a], off);
            acc1[a] += __shfl_xor_sync(0xffffffffu, acc1[a], off);
        }

    if (lane < 2) {
        const float* accp = lane == 0 ? acc0 : acc1;
        const int row = row0 + lane;
        const int mode = s_mode;
        const long base = (long)row * A_DIM;
        float masked[A_DIM];
        float m = -3.0e38f;
#pragma unroll
        for (int a = 0; a < A_DIM; a++) {
            const float l = accp[a] + __ldg(&b2[a]);
            bool valid;
            if (mode == 1)      valid = ((const int*)valid_mask)[base + a] != 0;
            else if (mode == 2) valid = ((const float*)valid_mask)[base + a] != 0.0f;
            else if (mode == 0) valid = ((const unsigned char*)valid_mask)[base + a] != 0;
            else                valid = ((const unsigned short*)valid_mask)[base + a] != 0;
            masked[a] = valid ? l : -1e9f;
            m = fmaxf(m, masked[a]);
        }
        float s = 0.f;
#pragma unroll
        for (int a = 0; a < A_DIM; a++) s += expf(masked[a] - m);
        const float lse = m + logf(s);

        int pred = 0;
        float best = masked[0];
#pragma unroll
        for (int a = 1; a < A_DIM; a++)
            if (masked[a] > best) { best = masked[a]; pred = a; }

        const int gold = real_actions[row];
        const float loss = masked[gold] - lse;

        if (write_pred) {
            out[row]     = (float)pred;
            out[B + row] = loss;
        } else {
            out[row] = loss;
        }
    }
}

// ---------------------------------------------------------------- launch --
extern "C" void kernel_launch(void* const* d_in, const int* in_sizes, int n_in,
                              void* d_out, int out_size)
{
    const float* buffer_h = (const float*)d_in[0];
    const float* stack_h  = (const float*)d_in[1];
    const float* output_h = (const float*)d_in[2];
    const float* action_h = (const float*)d_in[3];
    const float* W1 = (const float*)d_in[4];
    const float* b1 = (const float*)d_in[5];
    const float* W2 = (const float*)d_in[6];
    const float* b2 = (const float*)d_in[7];
    const void* valid_mask = d_in[8];
    const int* real_actions = (const int*)d_in[9];
    float* out = (float*)d_out;

    const int B = in_sizes[0] / H_DIM;  // 16384

    const size_t totalA4 = (size_t)B * K_DIM / 4;
    splitA_kernel<<<(unsigned)((totalA4 + 255) / 256), 256>>>(buffer_h, stack_h,
                                                              output_h, action_h);
    splitB_kernel<<<dim3(H_DIM / 32, K_DIM / 32), dim3(32, 8)>>>(W1);

    const int smem1 = 2 * STAGEB;  // 48 KB
    cudaFuncSetAttribute(gemm1_fp16_kernel,
                         cudaFuncAttributeMaxDynamicSharedMemorySize, smem1);
    dim3 grid1(H_DIM / BN, B / BM);   // (8, 256) = 2048 tiles
    gemm1_fp16_kernel<<<grid1, 256, smem1>>>(b1);

    static const size_t smem2 = (size_t)A_DIM * H_DIM * sizeof(float);
    cudaFuncSetAttribute(stage2_kernel,
                         cudaFuncAttributeMaxDynamicSharedMemorySize, (int)smem2);
    const int write_pred = (out_size >= 2 * B) ? 1 : 0;
    dim3 grid2(B / 32);
    stage2_kernel<<<grid2, 512, smem2>>>(W2, b2, valid_mask, real_actions,
                                         out, B, write_pred);
}